// round 11
// baseline (speedup 1.0000x reference)
#include <cuda_runtime.h>
#include <math.h>

#define Bsz 128
#define Tt  256
#define Hd  1024
#define BT  (Bsz * Tt)
#define BH  (Bsz * Hd)

// Scratch (device globals)
__device__ __align__(16) unsigned g_xfrag[(size_t)BT * Hd]; // x fragments (128 MiB)
__device__ __align__(16) unsigned g_wifrag[Hd * Hd];        // Wi0 in B-fragment layout (4 MiB)
__device__ __align__(16) float g_h0f[BH];                   // final h0 (fp32)
__device__ __align__(16) float g_part[4][BH];               // B partials: Gi1 kh0/1, Gh1 kh0/1
__device__ __align__(16) float g_ringP[2][BH];              // x@Wi0 ring (full K, combined)
__device__ __align__(16) unsigned g_h0frag[4][BH];          // h0 fragments, depth-4 ring
__device__ __align__(16) unsigned g_h1frag[2][BH];          // h1 fragments, parity
__device__ int g_cntB[16];                                  // B tile combine counters
__device__ int g_cntPall;                                   // Gp arrivals (16/phase)
__device__ int g_barA, g_barB;                              // group phase barriers

// ---------------------------------------------------------------------------
__device__ __forceinline__ unsigned f2tf(float x) {
    unsigned u; asm("cvt.rna.tf32.f32 %0, %1;" : "=r"(u) : "f"(x)); return u;
}
__device__ __forceinline__ int ld_acq(const int* a) {
    int v; asm volatile("ld.acquire.gpu.s32 %0, [%1];" : "=r"(v) : "l"(a) : "memory"); return v;
}
__device__ __forceinline__ void red_release(int* a) {
    asm volatile("red.release.gpu.global.add.s32 [%0], 1;" :: "l"(a) : "memory");
}
__device__ __forceinline__ void wait_ge(const int* a, int tgt) {
    if (ld_acq(a) >= tgt) return;
    while (ld_acq(a) < tgt) __nanosleep(32);
}
__device__ __forceinline__ void prefetchL2(const void* p) {
    asm volatile("prefetch.global.L2 [%0];" :: "l"(p));
}

#define MMA_TF32(C, A, B)                                                     \
    asm volatile(                                                             \
        "mma.sync.aligned.m16n8k8.row.col.f32.tf32.tf32.f32 "                 \
        "{%0,%1,%2,%3}, {%4,%5,%6,%7}, {%8,%9}, {%0,%1,%2,%3};"               \
        : "+f"((C)[0]), "+f"((C)[1]), "+f"((C)[2]), "+f"((C)[3])              \
        : "r"((A).x), "r"((A).y), "r"((A).z), "r"((A).w),                     \
          "r"((B).x), "r"((B).y))

// A-fragment index of (row b, col n): uint idx = ((k8*8 + mtile)*32 + lane)*4 + reg
__device__ __forceinline__ int frag_idx(int b, int n) {
    int kc = n & 7;
    int lane = (b & 7) * 4 + (kc & 3);
    int reg  = ((b >> 3) & 1) + ((kc >> 2) << 1);
    return ((((n >> 3) << 3) + (b >> 4)) * 32 + lane) * 4 + reg;
}

// ---------------------------------------------------------------------------
__global__ void init_kernel(const float* __restrict__ h0in)
{
    int idx = blockIdx.x * blockDim.x + threadIdx.x;
    if (idx < 16) g_cntB[idx] = 0;
    if (idx == 16) { g_barA = 0; g_barB = 0; g_cntPall = 0; }
    for (int e = idx; e < 2 * BH; e += gridDim.x * blockDim.x) {
        int which = e >> 17;
        int r = e & (BH - 1);
        int b = r >> 10, n = r & 1023;
        unsigned v = f2tf(h0in[which * Hd + n]);
        if (which == 0) g_h0frag[3][frag_idx(b, n)] = v;   // A(0) reads slot 3
        else            g_h1frag[1][frag_idx(b, n)] = v;   // Gh1(1) reads slot 1
    }
}

__global__ void xprep_kernel(const float* __restrict__ x)
{
    const int total = BT * Hd / 4;
    for (int e = blockIdx.x * blockDim.x + threadIdx.x; e < total;
         e += gridDim.x * blockDim.x) {
        int n  = (e & 255) * 4;
        int bt = e >> 8;
        int b  = bt >> 8;
        int t  = bt & 255;
        float4 v = *(const float4*)(x + (size_t)e * 4);
        unsigned* dst = g_xfrag + (size_t)t * BH;
        dst[frag_idx(b, n + 0)] = f2tf(v.x);
        dst[frag_idx(b, n + 1)] = f2tf(v.y);
        dst[frag_idx(b, n + 2)] = f2tf(v.z);
        dst[frag_idx(b, n + 3)] = f2tf(v.w);
    }
}

// Wi0 -> B-fragment layout in GMEM: idx = ((k8*128 + n>>3)*32 + (n&7)*4 + (k&3))*2 + ((k&7)>>2)
__global__ void wprep_kernel(const float* __restrict__ Wi)
{
    const int total = Hd * Hd / 4;
    for (int e = blockIdx.x * blockDim.x + threadIdx.x; e < total;
         e += gridDim.x * blockDim.x) {
        int k  = e >> 8;
        int c4 = e & 255;
        float4 v = *(const float4*)(Wi + (size_t)k * Hd + c4 * 4);
        float vv[4] = {v.x, v.y, v.z, v.w};
#pragma unroll
        for (int j = 0; j < 4; j++) {
            int n = c4 * 4 + j;
            int idx = (((k >> 3) * 128 + (n >> 3)) * 32 + (n & 7) * 4 + (k & 3)) * 2
                      + ((k & 7) >> 2);
            g_wifrag[idx] = f2tf(vv[j]);
        }
    }
}

// ---------------------------------------------------------------------------
// Persistent kernel. 144 blocks x 512 threads.
//   bid 0..63:    role A (Gh0): N-tile 16, FULL K=1024 in-block; in-block epilogue.
//   bid 64..127:  role B (Gi1/Gh1): as R9 (N-tile 64, K-half, 4-way combine).
//   bid 128..143: role P (x@Wi0): N-tile 64, FULL K in-block, ring depth 2,
//                 weights streamed from g_wifrag (L2-resident).
// ---------------------------------------------------------------------------
extern __shared__ unsigned smemAll[];   // Bw up to 128KB at 0; red 32KB at +128KB

__global__ __launch_bounds__(512, 1) void persistent_kernel(
    const float* __restrict__ Wi, const float* __restrict__ bi,
    const float* __restrict__ Wh, const float* __restrict__ bh,
    float* __restrict__ out)
{
    const int bid  = blockIdx.x;
    const int tid  = threadIdx.x;
    const int lane = tid & 31;
    const int wid  = tid >> 5;
    const int wm   = wid & 7;
    const int kg   = wid >> 3;

    unsigned* Bw = smemAll;
    float4*  red = (float4*)(smemAll + 32768);

    if (bid < 64) {
        // ============================ ROLE A ============================
        const int n0 = bid * 16;
        // preload Wh0 tile [1024 x 16] into fragment smem (64KB)
#pragma unroll 4
        for (int i = 0; i < 8; i++) {
            int idx = tid + 512 * i;              // 4096 float4
            int krow = idx >> 2, c4 = idx & 3;
            float4 w = *(const float4*)(Wh + (size_t)krow * Hd + n0 + c4 * 4);
            int k8 = krow >> 3, kk = krow & 7, nt = c4 >> 1, ccb = (c4 & 1) * 4;
            float vv[4] = {w.x, w.y, w.z, w.w};
#pragma unroll
            for (int j = 0; j < 4; j++)
                Bw[((k8 * 2 + nt) * 32 + (ccb + j) * 4 + (kk & 3)) * 2 + (kk >> 2)] = f2tf(vv[j]);
        }
        __syncthreads();

        for (int p = 0; p < Tt; ++p) {
            if (tid == 0 && p > 0) wait_ge(&g_barA, 64 * p);
            __syncthreads();

            const uint4* abase = (const uint4*)g_h0frag[(p - 1) & 3]
                                 + ((size_t)(kg * 64) * 8 + wm) * 32 + lane;
            float c[2][4];
#pragma unroll
            for (int nt = 0; nt < 2; nt++)
#pragma unroll
                for (int r = 0; r < 4; r++) c[nt][r] = 0.0f;

            uint4 pa[8];
#pragma unroll
            for (int i = 0; i < 8; i++) pa[i] = __ldcg(abase + i * 256);

#pragma unroll 8
            for (int k8l = 0; k8l < 64; k8l++) {
                uint4 a = pa[k8l & 7];
                if (k8l < 56) pa[k8l & 7] = __ldcg(abase + (k8l + 8) * 256);
                const int k8 = kg * 64 + k8l;
                uint2 b0 = *(const uint2*)&Bw[((k8 * 2 + 0) * 32 + lane) * 2];
                uint2 b1 = *(const uint2*)&Bw[((k8 * 2 + 1) * 32 + lane) * 2];
                MMA_TF32(c[0], a, b0);
                MMA_TF32(c[1], a, b1);
            }

            if (kg == 1) {
#pragma unroll
                for (int nt = 0; nt < 2; nt++)
                    red[(wm * 2 + nt) * 32 + lane] =
                        make_float4(c[nt][0], c[nt][1], c[nt][2], c[nt][3]);
            }
            __syncthreads();
            if (kg == 0) {
#pragma unroll
                for (int nt = 0; nt < 2; nt++) {
                    float4 r = red[(wm * 2 + nt) * 32 + lane];
                    c[nt][0] += r.x; c[nt][1] += r.y; c[nt][2] += r.z; c[nt][3] += r.w;
                }
            }
            // waits: Gp ring ready (pre-satisfied) + WAR on h0frag slot (pre-satisfied)
            if (tid == 0) wait_ge(&g_cntPall, 16 * (p + 1));
            if (tid == 1 && p >= 4) wait_ge(&g_barB, 64 * (p - 3));
            __syncthreads();

            if (kg == 0) {
                const int gq = lane >> 2, tq = lane & 3;
                unsigned* dstf = g_h0frag[p & 3];
                const float* rp = g_ringP[p & 1];
#pragma unroll
                for (int nt = 0; nt < 2; nt++) {
                    const int n = n0 + nt * 8 + 2 * tq;
                    const int r0 = wm * 16 + gq, r1 = r0 + 8;
                    float2 q0 = *(const float2*)&rp[(size_t)r0 * Hd + n];
                    float2 q1 = *(const float2*)&rp[(size_t)r1 * Hd + n];
                    float2 bb1 = *(const float2*)&bi[n];
                    float2 bb2 = *(const float2*)&bh[n];
                    float bs0 = bb1.x + bb2.x, bs1 = bb1.y + bb2.y;
                    float v00 = tanhf(c[nt][0] + q0.x + bs0);
                    float v01 = tanhf(c[nt][1] + q0.y + bs1);
                    float v10 = tanhf(c[nt][2] + q1.x + bs0);
                    float v11 = tanhf(c[nt][3] + q1.y + bs1);
                    if (p == Tt - 1) {
                        *(float2*)&g_h0f[(size_t)r0 * Hd + n] = make_float2(v00, v01);
                        *(float2*)&g_h0f[(size_t)r1 * Hd + n] = make_float2(v10, v11);
                    }
                    dstf[frag_idx(r0, n + 0)] = f2tf(v00);
                    dstf[frag_idx(r0, n + 1)] = f2tf(v01);
                    dstf[frag_idx(r1, n + 0)] = f2tf(v10);
                    dstf[frag_idx(r1, n + 1)] = f2tf(v11);
                }
            }
            __syncthreads();
            if (tid == 0) red_release(&g_barA);
        }
    } else if (bid < 128) {
        // ============================ ROLE B ============================
        const int part = 1 + ((bid - 64) >> 5);   // 1=Gi1, 2=Gh1
        const int sub  = (bid - 64) & 31;
        const int tile = sub >> 1;
        const int kh   = sub & 1;
        const int n0   = tile * 64;
        const int kstart = kh * 512;

        const float* wbase = (part == 1) ? Wi + (size_t)Hd * Hd
                                         : Wh + (size_t)Hd * Hd;
#pragma unroll 4
        for (int i = 0; i < 16; i++) {
            int idx = tid + 512 * i;
            int krow = idx >> 4, c4 = idx & 15;
            float4 w = *(const float4*)(wbase + (size_t)(kstart + krow) * Hd + n0 + c4 * 4);
            int k8 = krow >> 3, kk = krow & 7, ntile = c4 >> 1;
            int base = ((k8 * 8 + ntile) * 32 + (c4 & 1) * 16 + (kk & 3)) * 2 + (kk >> 2);
            Bw[base +  0] = f2tf(w.x);
            Bw[base +  8] = f2tf(w.y);
            Bw[base + 16] = f2tf(w.z);
            Bw[base + 24] = f2tf(w.w);
        }
        __syncthreads();

        float* mp = g_part[(part - 1) * 2 + kh];

        for (int p = 1; p <= Tt; ++p) {
            if (tid == 0) wait_ge(&g_barA, 64 * p);
            if (tid == 1 && p > 1) wait_ge(&g_barB, 64 * (p - 1));
            __syncthreads();

            const unsigned* afrag = (part == 1) ? g_h0frag[(p - 1) & 3]
                                                : g_h1frag[p & 1];
            const uint4* abase = ((const uint4*)afrag)
                                 + ((size_t)(kh * 64 + kg * 32) * 8 + wm) * 32 + lane;

            float c[8][4];
#pragma unroll
            for (int nt = 0; nt < 8; nt++)
#pragma unroll
                for (int r = 0; r < 4; r++) c[nt][r] = 0.0f;

            uint4 pa[8];
#pragma unroll
            for (int i = 0; i < 8; i++) pa[i] = __ldcg(abase + i * 256);

#pragma unroll 8
            for (int k8l = 0; k8l < 32; k8l++) {
                uint4 a = pa[k8l & 7];
                if (k8l < 24) pa[k8l & 7] = __ldcg(abase + (k8l + 8) * 256);
                const int k8 = kg * 32 + k8l;
#pragma unroll
                for (int nt = 0; nt < 8; nt++) {
                    uint2 bfr = *(const uint2*)&Bw[(((k8 << 3) + nt) * 32 + lane) * 2];
                    MMA_TF32(c[nt], a, bfr);
                }
            }

            if (kg == 1) {
#pragma unroll
                for (int q = 0; q < 8; q++)
                    red[(wm * 8 + q) * 32 + lane] =
                        make_float4(c[q][0], c[q][1], c[q][2], c[q][3]);
            }
            __syncthreads();
            if (kg == 0) {
#pragma unroll
                for (int q = 0; q < 8; q++) {
                    float4 r = red[(wm * 8 + q) * 32 + lane];
                    c[q][0] += r.x; c[q][1] += r.y; c[q][2] += r.z; c[q][3] += r.w;
                }
                const int gq = lane >> 2, tq = lane & 3;
#pragma unroll
                for (int nt = 0; nt < 8; nt++) {
                    int row = wm * 16 + gq;
                    int col = n0 + nt * 8 + 2 * tq;
                    *(float2*)&mp[(size_t)row * Hd + col] = make_float2(c[nt][0], c[nt][1]);
                    *(float2*)&mp[(size_t)(row + 8) * Hd + col] = make_float2(c[nt][2], c[nt][3]);
                }
            }
            __syncthreads();

            if (tid == 0) {
                red_release(&g_cntB[tile]);
                wait_ge(&g_cntB[tile], 4 * p);
            }
            __syncthreads();

            const int chunk = (part - 1) * 2 + kh;
            const int row = chunk * 32 + (tid >> 4);
            const int n   = n0 + (tid & 15) * 4;
            const int tt  = p - 1;
            unsigned* dstf = g_h1frag[(p - 1) & 1];
            float4 s2 = __ldcg((const float4*)&g_part[0][(size_t)row * Hd + n]);
            float4 s3 = __ldcg((const float4*)&g_part[1][(size_t)row * Hd + n]);
            float4 s4 = __ldcg((const float4*)&g_part[2][(size_t)row * Hd + n]);
            float4 s5 = __ldcg((const float4*)&g_part[3][(size_t)row * Hd + n]);
            float4 b1 = *(const float4*)&bi[Hd + n];
            float4 b2 = *(const float4*)&bh[Hd + n];
            float r0 = tanhf(s2.x + s3.x + s4.x + s5.x + b1.x + b2.x);
            float r1 = tanhf(s2.y + s3.y + s4.y + s5.y + b1.y + b2.y);
            float r2 = tanhf(s2.z + s3.z + s4.z + s5.z + b1.z + b2.z);
            float r3 = tanhf(s2.w + s3.w + s4.w + s5.w + b1.w + b2.w);
            *(float4*)&out[((size_t)row * Tt + tt) * Hd + n] = make_float4(r0, r1, r2, r3);
            dstf[frag_idx(row, n + 0)] = f2tf(r0);
            dstf[frag_idx(row, n + 1)] = f2tf(r1);
            dstf[frag_idx(row, n + 2)] = f2tf(r2);
            dstf[frag_idx(row, n + 3)] = f2tf(r3);

            __syncthreads();
            if (tid == 0) red_release(&g_barB);
        }
    } else {
        // ============================ ROLE P ============================
        const int tileP = bid - 128;          // 0..15
        const int n0 = tileP * 64;
        const uint2* wf = (const uint2*)g_wifrag;

        for (int p = 0; p < Tt; ++p) {
            if (tid == 0 && p >= 2) wait_ge(&g_barA, 64 * (p - 1));
            __syncthreads();

            const uint4* abase = (const uint4*)(g_xfrag + (size_t)p * BH)
                                 + ((size_t)(kg * 64) * 8 + wm) * 32 + lane;
            float c[8][4];
#pragma unroll
            for (int nt = 0; nt < 8; nt++)
#pragma unroll
                for (int r = 0; r < 4; r++) c[nt][r] = 0.0f;

            uint4 pa[8];
#pragma unroll
            for (int i = 0; i < 8; i++) pa[i] = __ldcg(abase + i * 256);

#pragma unroll 4
            for (int k8l = 0; k8l < 64; k8l++) {
                uint4 a = pa[k8l & 7];
                if (k8l < 56) pa[k8l & 7] = __ldcg(abase + (k8l + 8) * 256);
                const int k8 = kg * 64 + k8l;
                uint2 bfr[8];
#pragma unroll
                for (int nt = 0; nt < 8; nt++)
                    bfr[nt] = __ldcg(wf + (((size_t)k8 * 128 + tileP * 8 + nt) * 32 + lane));
#pragma unroll
                for (int nt = 0; nt < 8; nt++)
                    MMA_TF32(c[nt], a, bfr[nt]);
            }

            if (kg == 1) {
#pragma unroll
                for (int q = 0; q < 8; q++)
                    red[(wm * 8 + q) * 32 + lane] =
                        make_float4(c[q][0], c[q][1], c[q][2], c[q][3]);
            }
            __syncthreads();
            if (kg == 0) {
                float* rp = g_ringP[p & 1];
#pragma unroll
                for (int q = 0; q < 8; q++) {
                    float4 r = red[(wm * 8 + q) * 32 + lane];
                    c[q][0] += r.x; c[q][1] += r.y; c[q][2] += r.z; c[q][3] += r.w;
                }
                const int gq = lane >> 2, tq = lane & 3;
#pragma unroll
                for (int nt = 0; nt < 8; nt++) {
                    int row = wm * 16 + gq;
                    int col = n0 + nt * 8 + 2 * tq;
                    *(float2*)&rp[(size_t)row * Hd + col] = make_float2(c[nt][0], c[nt][1]);
                    *(float2*)&rp[(size_t)(row + 8) * Hd + col] = make_float2(c[nt][2], c[nt][3]);
                }
            }
            // prefetch next phase's x slice (512KB total over 16 blocks)
            if (p + 1 < Tt && tid < 256)
                prefetchL2((const char*)(g_xfrag + (size_t)(p + 1) * BH)
                           + ((size_t)tileP * 256 + tid) * 128);
            __syncthreads();
            if (tid == 0) red_release(&g_cntPall);
        }
    }
}

// ---------------------------------------------------------------------------
__global__ void finalize_kernel(float* __restrict__ out)
{
    int idx = blockIdx.x * blockDim.x + threadIdx.x;
    if (idx >= BH) return;
    int b = idx / Hd, h = idx % Hd;
    float* hn = out + (size_t)BT * Hd;
    hn[((size_t)b * 2 + 0) * Hd + h] = g_h0f[(size_t)b * Hd + h];
    hn[((size_t)b * 2 + 1) * Hd + h] = out[((size_t)b * Tt + (Tt - 1)) * Hd + h];
}

// ---------------------------------------------------------------------------
extern "C" void kernel_launch(void* const* d_in, const int* in_sizes, int n_in,
                              void* d_out, int out_size)
{
    const float* x    = (const float*)d_in[0];   // [B,T,H]
    const float* h0in = (const float*)d_in[1];   // [1,L,H]
    const float* Wi   = (const float*)d_in[2];   // [L,H,H]
    const float* bi   = (const float*)d_in[3];   // [L,H]
    const float* Wh   = (const float*)d_in[4];   // [L,H,H]
    const float* bh   = (const float*)d_in[5];   // [L,H]
    float* out = (float*)d_out;                  // [B,T,H] then [B,L,H]

    init_kernel<<<256, 256>>>(h0in);
    xprep_kernel<<<8192, 256>>>(x);
    wprep_kernel<<<1024, 256>>>(Wi);

    cudaFuncSetAttribute(persistent_kernel,
                         cudaFuncAttributeMaxDynamicSharedMemorySize, 163840);
    persistent_kernel<<<144, 512, 163840>>>(Wi, bi, Wh, bh, out);

    finalize_kernel<<<(BH + 255) / 256, 256>>>(out);
}

// round 12
// speedup vs baseline: 3.5571x; 3.5571x over previous
#include <cuda_runtime.h>
#include <cuda_fp16.h>
#include <math.h>

#define Bsz 128
#define Tt  256
#define Hd  1024
#define BT  (Bsz * Tt)
#define BH  (Bsz * Hd)

// Scratch (device globals). Fragments are fp16 packed as half2-in-u32.
__device__ __align__(16) unsigned g_xfrag[(size_t)BT * Hd / 2]; // x fragments (64 MiB)
__device__ __align__(16) float g_h0f[BH];                   // final h0 (fp32)
__device__ __align__(16) float g_part[8][BH];               // per-phase GEMM partials (fp32)
__device__ __align__(16) unsigned g_h0frag[2][BH / 2];      // h0 fragments, parity
__device__ __align__(16) unsigned g_h1frag[2][BH / 2];      // h1 fragments, parity
__device__ int g_cntA[16], g_cntB[16];                      // tile combine counters
__device__ int g_barA, g_barB;                              // group phase barriers

// ---------------------------------------------------------------------------
__device__ __forceinline__ unsigned f2h2(float lo, float hi) {
    __half2 h = __floats2half2_rn(lo, hi);
    return *(unsigned*)&h;
}
__device__ __forceinline__ int ld_acq(const int* a) {
    int v; asm volatile("ld.acquire.gpu.s32 %0, [%1];" : "=r"(v) : "l"(a) : "memory"); return v;
}
__device__ __forceinline__ void red_release(int* a) {
    asm volatile("red.release.gpu.global.add.s32 [%0], 1;" :: "l"(a) : "memory");
}
__device__ __forceinline__ void wait_ge(const int* a, int tgt) {
    if (ld_acq(a) >= tgt) return;
    while (ld_acq(a) < tgt) __nanosleep(32);
}
__device__ __forceinline__ void prefetchL2(const void* p) {
    asm volatile("prefetch.global.L2 [%0];" :: "l"(p));
}

// m16n8k16 fp16 MMA, fp32 accumulate
#define MMA_F16(C, A, B)                                                      \
    asm volatile(                                                             \
        "mma.sync.aligned.m16n8k16.row.col.f32.f16.f16.f32 "                  \
        "{%0,%1,%2,%3}, {%4,%5,%6,%7}, {%8,%9}, {%0,%1,%2,%3};"               \
        : "+f"((C)[0]), "+f"((C)[1]), "+f"((C)[2]), "+f"((C)[3])              \
        : "r"((A).x), "r"((A).y), "r"((A).z), "r"((A).w),                     \
          "r"((B).x), "r"((B).y))

// u32 index of the half2 holding elements (b, n) and (b, n+1); n even.
// m16n8k16 A-layout: lane = (r&7)*4 + ((kc>>1)&3); reg = (r>=8) + 2*(kc>=8)
__device__ __forceinline__ int fidx2(int b, int n) {
    int kc = n & 15;
    int lane = (b & 7) * 4 + ((kc >> 1) & 3);
    int reg  = ((b >> 3) & 1) + ((kc >> 3) << 1);
    return (((n >> 4) * 8 + (b >> 4)) * 32 + lane) * 4 + reg;
}

// ---------------------------------------------------------------------------
// Init: zero sync state, fill initial-state fragment buffers (fp16)
// ---------------------------------------------------------------------------
__global__ void init_kernel(const float* __restrict__ h0in)
{
    int idx = blockIdx.x * blockDim.x + threadIdx.x;
    if (idx < 16) { g_cntA[idx] = 0; g_cntB[idx] = 0; }
    if (idx == 16) { g_barA = 0; g_barB = 0; }
    for (int e = idx; e < 2 * (BH / 2); e += gridDim.x * blockDim.x) {
        int which = e >> 16;               // 0: layer0, 1: layer1  (BH/2 = 65536)
        int r = e & (BH / 2 - 1);
        int b = r >> 9;                    // 512 half2 per row
        int n = (r & 511) * 2;
        unsigned v = f2h2(h0in[which * Hd + n], h0in[which * Hd + n + 1]);
        if (which == 0) g_h0frag[1][fidx2(b, n)] = v;
        else            g_h1frag[1][fidx2(b, n)] = v;
    }
}

// ---------------------------------------------------------------------------
// xprep: x [B,T,H] fp32 -> per-token fp16 fragments in g_xfrag (one-shot).
// ---------------------------------------------------------------------------
__global__ void xprep_kernel(const float* __restrict__ x)
{
    const int total = BT * Hd / 4;
    for (int e = blockIdx.x * blockDim.x + threadIdx.x; e < total;
         e += gridDim.x * blockDim.x) {
        int n  = (e & 255) * 4;
        int bt = e >> 8;
        int b  = bt >> 8;
        int t  = bt & 255;
        float4 v = *(const float4*)(x + (size_t)e * 4);
        unsigned* dst = g_xfrag + (size_t)t * (BH / 2);
        dst[fidx2(b, n + 0)] = f2h2(v.x, v.y);
        dst[fidx2(b, n + 2)] = f2h2(v.z, v.w);
    }
}

// ---------------------------------------------------------------------------
// Persistent kernel — identical structure to the 3123us baseline, fp16 math.
// Grid = 128 blocks x 512 threads, 1 block/SM.
//   part = bid/32: 0=Gh0 [A], 1=Gi1 [B], 2=Gh1 [B], 3=Gp=x_p@Wi0 [A]
//   sub = bid%32: tile = sub>>1 (N-tile of 64), kh = sub&1 (K-half of 512).
// Warp layout: wm = wid&7 (M-tile of 16), kg = wid>>3 (K-group of 256).
// Per warp: 16 k16-steps x 8 ntiles = 128 m16n8k16 MMAs; disjoint A addresses.
// ---------------------------------------------------------------------------
extern __shared__ unsigned smemAll[];   // Bw: 16384 u32 (64KB) + red: 32KB

__global__ __launch_bounds__(512, 1) void persistent_kernel(
    const float* __restrict__ Wi, const float* __restrict__ bi,
    const float* __restrict__ Wh, const float* __restrict__ bh,
    float* __restrict__ out)
{
    const int part = blockIdx.x >> 5;     // 0..3
    const int sub  = blockIdx.x & 31;
    const int tile = sub >> 1;
    const int kh   = sub & 1;
    const bool isA = (part == 0 || part == 3);

    const int tid  = threadIdx.x;
    const int lane = tid & 31;
    const int wid  = tid >> 5;
    const int wm   = wid & 7;             // M-tile (16 rows)
    const int kg   = wid >> 3;            // K-group (16 k16-steps of this K-half)
    const int n0   = tile * 64;
    const int kstart = kh * 512;

    unsigned* Bw = smemAll;                       // [32 k16][8 nt][32 lane][2 reg]
    float4*  red = (float4*)(smemAll + 16384);    // [8 wm][8 q][32 lane]

    const float* wbase = (part == 0) ? Wh
                       : (part == 1) ? Wi + (size_t)Hd * Hd
                       : (part == 2) ? Wh + (size_t)Hd * Hd
                                     : Wi;

    // ---- one-time weight preload: pack k-pairs into fp16 fragment smem ----
    // B-frag: lane = n_in*4 + ((kk&7)>>1), reg = kk>>3, halves along k.
#pragma unroll 4
    for (int i = 0; i < 8; i++) {
        int idx = tid + 512 * i;              // 4096 = 256 k-pairs x 16 col-groups
        int kp  = idx >> 4;                   // krow pair: rows 2kp, 2kp+1
        int c4  = idx & 15;
        int krow0 = kstart + 2 * kp;
        float4 w0 = *(const float4*)(wbase + (size_t)krow0 * Hd + n0 + c4 * 4);
        float4 w1 = *(const float4*)(wbase + (size_t)(krow0 + 1) * Hd + n0 + c4 * 4);
        int kk  = (2 * kp) & 15;              // even
        int k16 = (2 * kp) >> 4;              // 0..31
        float a0[4] = {w0.x, w0.y, w0.z, w0.w};
        float a1[4] = {w1.x, w1.y, w1.z, w1.w};
#pragma unroll
        for (int j = 0; j < 4; j++) {
            int n  = c4 * 4 + j;
            int nt = n >> 3, n_in = n & 7;
            Bw[((k16 * 8 + nt) * 32 + n_in * 4 + ((kk & 7) >> 1)) * 2 + (kk >> 3)] =
                f2h2(a0[j], a1[j]);
        }
    }
    __syncthreads();

    float* mp = g_part[(part == 3) ? (6 + kh) : (part * 2 + kh)];

    const int pstart = isA ? 0 : 1;
    const int pend   = isA ? Tt - 1 : Tt;

    for (int p = pstart; p <= pend; ++p) {
        // ---- entry flow wait ----
        if (tid < 2) {
            if (isA) {
                if (tid == 0 && p > 0) wait_ge(&g_barA, 64 * p);
            } else {
                if (tid == 0) wait_ge(&g_barA, 64 * p);
                if (tid == 1 && p > 1) wait_ge(&g_barB, 64 * (p - 1));
            }
        }
        __syncthreads();

        const unsigned* afrag =
            (part == 0) ? g_h0frag[(p - 1) & 1] :
            (part == 1) ? g_h0frag[(p - 1) & 1] :
            (part == 2) ? g_h1frag[p & 1]
                        : g_xfrag + (size_t)p * (BH / 2);
        // warp's disjoint A stream: k16 range [kh*32 + kg*16, +16), m-tile wm
        const uint4* abase = ((const uint4*)afrag)
                             + ((size_t)(kh * 32 + kg * 16) * 8 + wm) * 32 + lane;

        float c[8][4];
#pragma unroll
        for (int nt = 0; nt < 8; nt++)
#pragma unroll
            for (int r = 0; r < 4; r++) c[nt][r] = 0.0f;

        uint4 pa[8];
#pragma unroll
        for (int i = 0; i < 8; i++)
            pa[i] = __ldcg(abase + i * 256);

#pragma unroll
        for (int k16l = 0; k16l < 16; k16l++) {
            uint4 a = pa[k16l & 7];
            if (k16l < 8)
                pa[k16l & 7] = __ldcg(abase + (k16l + 8) * 256);
            const int k16 = kg * 16 + k16l;
#pragma unroll
            for (int nt = 0; nt < 8; nt++) {
                uint2 bfr = *(const uint2*)&Bw[(((k16 << 3) + nt) * 32 + lane) * 2];
                MMA_F16(c[nt], a, bfr);
            }
        }

        // ---- kg combine: kg1 -> smem, kg0 adds; kg0 stores partial ----
        if (kg == 1) {
#pragma unroll
            for (int q = 0; q < 8; q++)
                red[(wm * 8 + q) * 32 + lane] =
                    make_float4(c[q][0], c[q][1], c[q][2], c[q][3]);
        }
        __syncthreads();
        if (kg == 0) {
#pragma unroll
            for (int q = 0; q < 8; q++) {
                float4 r = red[(wm * 8 + q) * 32 + lane];
                c[q][0] += r.x; c[q][1] += r.y; c[q][2] += r.z; c[q][3] += r.w;
            }
            const int gq = lane >> 2, tq = lane & 3;
#pragma unroll
            for (int nt = 0; nt < 8; nt++) {
                int row = wm * 16 + gq;
                int col = n0 + nt * 8 + 2 * tq;
                *(float2*)&mp[(size_t)row * Hd + col] = make_float2(c[nt][0], c[nt][1]);
                *(float2*)&mp[(size_t)(row + 8) * Hd + col] = make_float2(c[nt][2], c[nt][3]);
            }
        }

        // full L2 prefetch of next-phase x slice (part 3): 1024 lines of 128B
        if (part == 3 && p + 1 < Tt) {
            const char* nx = (const char*)(g_xfrag
                              + (size_t)(p + 1) * (BH / 2) + (size_t)kh * 32768);
#pragma unroll
            for (int i = 0; i < 2; i++)
                prefetchL2(nx + ((size_t)tid + i * 512) * 128);
        }

        // ---- tile combine sync (4 contributors) + A's WAR wait ----
        __syncthreads();
        if (tid == 0) {
            int* cnt = isA ? &g_cntA[tile] : &g_cntB[tile];
            red_release(cnt);
            const int tgt = isA ? 4 * (p + 1) : 4 * p;
            wait_ge(cnt, tgt);
            if (isA && p >= 2)
                wait_ge(&g_barB, 64 * (p - 1));    // WAR on h0frag parity buffer
        }
        __syncthreads();

        // ---- distributed epilogue: 4 blocks/tile, each 32 rows x 64 cols ----
        const int chunk = isA ? ((part == 0 ? 0 : 2) + kh)
                              : ((part - 1) * 2 + kh);
        const int row = chunk * 32 + (tid >> 4);
        const int n   = n0 + (tid & 15) * 4;
        if (isA) {
            unsigned* dstf = g_h0frag[p & 1];
            float4 a = __ldcg((const float4*)&g_part[0][(size_t)row * Hd + n]);
            float4 b = __ldcg((const float4*)&g_part[1][(size_t)row * Hd + n]);
            float4 q = __ldcg((const float4*)&g_part[6][(size_t)row * Hd + n]);
            float4 s = __ldcg((const float4*)&g_part[7][(size_t)row * Hd + n]);
            float4 b1 = *(const float4*)&bi[n];
            float4 b2 = *(const float4*)&bh[n];
            float r0 = tanhf(a.x + b.x + q.x + s.x + b1.x + b2.x);
            float r1 = tanhf(a.y + b.y + q.y + s.y + b1.y + b2.y);
            float r2 = tanhf(a.z + b.z + q.z + s.z + b1.z + b2.z);
            float r3 = tanhf(a.w + b.w + q.w + s.w + b1.w + b2.w);
            if (p == Tt - 1)
                *(float4*)&g_h0f[(size_t)row * Hd + n] = make_float4(r0, r1, r2, r3);
            dstf[fidx2(row, n + 0)] = f2h2(r0, r1);
            dstf[fidx2(row, n + 2)] = f2h2(r2, r3);
        } else {
            const int tt = p - 1;
            unsigned* dstf = g_h1frag[(p - 1) & 1];
            float4 s2 = __ldcg((const float4*)&g_part[2][(size_t)row * Hd + n]);
            float4 s3 = __ldcg((const float4*)&g_part[3][(size_t)row * Hd + n]);
            float4 s4 = __ldcg((const float4*)&g_part[4][(size_t)row * Hd + n]);
            float4 s5 = __ldcg((const float4*)&g_part[5][(size_t)row * Hd + n]);
            float4 b1 = *(const float4*)&bi[Hd + n];
            float4 b2 = *(const float4*)&bh[Hd + n];
            float r0 = tanhf(s2.x + s3.x + s4.x + s5.x + b1.x + b2.x);
            float r1 = tanhf(s2.y + s3.y + s4.y + s5.y + b1.y + b2.y);
            float r2 = tanhf(s2.z + s3.z + s4.z + s5.z + b1.z + b2.z);
            float r3 = tanhf(s2.w + s3.w + s4.w + s5.w + b1.w + b2.w);
            *(float4*)&out[((size_t)row * Tt + tt) * Hd + n] =
                make_float4(r0, r1, r2, r3);
            dstf[fidx2(row, n + 0)] = f2h2(r0, r1);
            dstf[fidx2(row, n + 2)] = f2h2(r2, r3);
        }

        // ---- group phase arrival (release publishes this block's writes) ----
        __syncthreads();
        if (tid == 0) red_release(isA ? &g_barA : &g_barB);
    }
}

// ---------------------------------------------------------------------------
// Finalize: h_n[b][0] = h0_{T-1}, h_n[b][1] = h1_{T-1} (= out[:,T-1,:])
// ---------------------------------------------------------------------------
__global__ void finalize_kernel(float* __restrict__ out)
{
    int idx = blockIdx.x * blockDim.x + threadIdx.x;
    if (idx >= BH) return;
    int b = idx / Hd, h = idx % Hd;
    float* hn = out + (size_t)BT * Hd;
    hn[((size_t)b * 2 + 0) * Hd + h] = g_h0f[(size_t)b * Hd + h];
    hn[((size_t)b * 2 + 1) * Hd + h] = out[((size_t)b * Tt + (Tt - 1)) * Hd + h];
}

// ---------------------------------------------------------------------------
extern "C" void kernel_launch(void* const* d_in, const int* in_sizes, int n_in,
                              void* d_out, int out_size)
{
    const float* x    = (const float*)d_in[0];   // [B,T,H]
    const float* h0in = (const float*)d_in[1];   // [1,L,H]
    const float* Wi   = (const float*)d_in[2];   // [L,H,H]
    const float* bi   = (const float*)d_in[3];   // [L,H]
    const float* Wh   = (const float*)d_in[4];   // [L,H,H]
    const float* bh   = (const float*)d_in[5];   // [L,H]
    float* out = (float*)d_out;                  // [B,T,H] then [B,L,H]

    init_kernel<<<256, 256>>>(h0in);
    xprep_kernel<<<8192, 256>>>(x);

    cudaFuncSetAttribute(persistent_kernel,
                         cudaFuncAttributeMaxDynamicSharedMemorySize, 98304);
    persistent_kernel<<<128, 512, 98304>>>(Wi, bi, Wh, bh, out);

    finalize_kernel<<<(BH + 255) / 256, 256>>>(out);
}